// round 1
// baseline (speedup 1.0000x reference)
#include <cuda_runtime.h>
#include <math.h>

#define NEXP   8
#define DM     1024
#define DF     4096
#define NTOK   8192
#define TOPK   2
#define SEGCAP 4096
#define PTOT   (NEXP * SEGCAP)
#define LN_EPS 1e-5f

// ---------------- scratch (device globals: allocation-free) ----------------
__device__ int   g_cursor[NEXP];
__device__ int   g_pair_token[PTOT];
__device__ int   g_pair_id[NTOK * TOPK];
__device__ float g_wf[NTOK * TOPK];
__device__ float g_mean[NTOK];
__device__ float g_rstd[NTOK];
__device__ float g_Xg[(size_t)PTOT * DM];   // gathered LN1(x) per pair
__device__ float g_H [(size_t)PTOT * DF];   // activated hidden per pair
__device__ float g_Y [(size_t)PTOT * DM];   // expert output (then LN2'd in place)

// ---------------- utilities ----------------
__device__ __forceinline__ void row_stats_256(float s, float ss, int nelem,
                                              float& m_out, float& r_out) {
    __shared__ float sm[8], sq[8];
    int lane = threadIdx.x & 31, w = threadIdx.x >> 5;
#pragma unroll
    for (int o = 16; o; o >>= 1) {
        s  += __shfl_down_sync(0xffffffffu, s,  o);
        ss += __shfl_down_sync(0xffffffffu, ss, o);
    }
    if (lane == 0) { sm[w] = s; sq[w] = ss; }
    __syncthreads();
    if (threadIdx.x == 0) {
        float ts = 0.f, tq = 0.f;
#pragma unroll
        for (int j = 0; j < 8; j++) { ts += sm[j]; tq += sq[j]; }
        float m = ts / (float)nelem;
        float v = tq / (float)nelem - m * m;
        sm[0] = m; sq[0] = rsqrtf(v + LN_EPS);
    }
    __syncthreads();
    m_out = sm[0];
    r_out = sq[0];
}

// ---------------- kernels ----------------
__global__ void k_init() {
    if (threadIdx.x < NEXP) g_cursor[threadIdx.x] = 0;
}

// per-token LN1 statistics (one block per token, 256 thr, float4)
__global__ void k_stats(const float* __restrict__ x) {
    int n = blockIdx.x;
    const float4* xr = (const float4*)(x + (size_t)n * DM);
    float4 v = xr[threadIdx.x];
    float s  = v.x + v.y + v.z + v.w;
    float ss = v.x * v.x + v.y * v.y + v.z * v.z + v.w * v.w;
    float m, r;
    row_stats_256(s, ss, DM, m, r);
    if (threadIdx.x == 0) { g_mean[n] = m; g_rstd[n] = r; }
}

// routing: capacity penalty, softmax over K=2, scatter into per-expert segments
__global__ void k_route(const float* __restrict__ ew, const int* __restrict__ idx,
                        const float* __restrict__ cu, const float* __restrict__ cap) {
    int n = blockIdx.x * blockDim.x + threadIdx.x;
    if (n >= NTOK) return;
    int   e[TOPK];
    float w[TOPK];
#pragma unroll
    for (int k = 0; k < TOPK; k++) {
        e[k] = idx[n * TOPK + k];
        float pen = cu[e[k]] / (cap[e[k]] + 1e-8f);
        pen = fminf(fmaxf(pen, 0.f), 2.f);
        w[k] = ew[n * TOPK + k] * (1.f / (1.f + pen));
    }
    float m  = fmaxf(w[0], w[1]);
    float e0 = expf(w[0] - m), e1 = expf(w[1] - m);
    float inv = 1.f / (e0 + e1);
    g_wf[n * TOPK + 0] = e0 * inv;
    g_wf[n * TOPK + 1] = e1 * inv;
#pragma unroll
    for (int k = 0; k < TOPK; k++) {
        int pos = atomicAdd(&g_cursor[e[k]], 1);
        if (pos >= SEGCAP) pos = SEGCAP - 1;   // unreachable safety clamp
        int p = e[k] * SEGCAP + pos;
        g_pair_token[p] = n;
        g_pair_id[n * TOPK + k] = p;
    }
}

// gather + LN1 apply: Xg[p, :] = ((x[n]-m)*rstd)*ln1_w[e] + ln1_b[e]
__global__ void k_gather(const float* __restrict__ x,
                         const float* __restrict__ ln1w,
                         const float* __restrict__ ln1b) {
    int p = blockIdx.x;
    int e = p / SEGCAP, i = p % SEGCAP;
    int cnt = min(g_cursor[e], SEGCAP);
    if (i >= cnt) return;
    int   n = g_pair_token[p];
    float m = g_mean[n], r = g_rstd[n];
    const float4* xr = (const float4*)(x    + (size_t)n * DM);
    const float4* wr = (const float4*)(ln1w + (size_t)e * DM);
    const float4* br = (const float4*)(ln1b + (size_t)e * DM);
    float4*       o  = (float4*)(g_Xg + (size_t)p * DM);
    float4 v = xr[threadIdx.x], w = wr[threadIdx.x], b = br[threadIdx.x];
    float4 t;
    t.x = (v.x - m) * r * w.x + b.x;
    t.y = (v.y - m) * r * w.y + b.y;
    t.z = (v.z - m) * r * w.z + b.z;
    t.w = (v.w - m) * r * w.w + b.w;
    o[threadIdx.x] = t;
}

// GEMM1 (+fused dual-matrix swiglu path, fused activation)
// C[cnt, DF] = Xg_seg @ W[DM, DF]; tiles 128x64, K-tile 16, 256 thr, 8x4 micro
__global__ void __launch_bounds__(256) k_gemm1(const float* __restrict__ w1,
                                               const float* __restrict__ w2) {
    int e   = blockIdx.z;
    int cnt = min(g_cursor[e], SEGCAP);
    int rm  = blockIdx.y * 128;
    if (rm >= cnt) return;
    int  cn   = blockIdx.x * 64;
    int  act  = e % 3;           // 0: swiglu, 1: gelu, 2: relu
    bool dual = (act == 0);

    __shared__ float As[16][128];
    __shared__ float Bs[16][64];
    __shared__ float Cs[16][64];

    int tid = threadIdx.x;
    int ty = tid >> 4, tx = tid & 15;
    float acc1[8][4], acc2[8][4];
#pragma unroll
    for (int i = 0; i < 8; i++)
#pragma unroll
        for (int j = 0; j < 4; j++) { acc1[i][j] = 0.f; acc2[i][j] = 0.f; }

    const float* A  = g_Xg + (size_t)(e * SEGCAP + rm) * DM;
    const float* B1 = w1 + (size_t)e * DM * DF + cn;
    const float* B2 = w2 + (size_t)e * DM * DF + cn;

    for (int kt = 0; kt < DM; kt += 16) {
        // stage A transposed: As[k][row]
#pragma unroll
        for (int l = 0; l < 2; l++) {
            int idx = tid + l * 256;
            int row = idx >> 2;
            int kk  = (idx & 3) << 2;
            float4 v = make_float4(0.f, 0.f, 0.f, 0.f);
            if (rm + row < cnt)
                v = *(const float4*)(A + (size_t)row * DM + kt + kk);
            As[kk + 0][row] = v.x; As[kk + 1][row] = v.y;
            As[kk + 2][row] = v.z; As[kk + 3][row] = v.w;
        }
        // stage B (and B2 for swiglu)
        {
            int kk = tid >> 4, c = (tid & 15) << 2;
            *(float4*)&Bs[kk][c] = *(const float4*)(B1 + (size_t)(kt + kk) * DF + c);
            if (dual)
                *(float4*)&Cs[kk][c] = *(const float4*)(B2 + (size_t)(kt + kk) * DF + c);
        }
        __syncthreads();
#pragma unroll
        for (int k = 0; k < 16; k++) {
            float4 a0 = *(const float4*)&As[k][ty * 4];
            float4 a1 = *(const float4*)&As[k][ty * 4 + 64];
            float4 b  = *(const float4*)&Bs[k][tx * 4];
            float ar[8] = {a0.x, a0.y, a0.z, a0.w, a1.x, a1.y, a1.z, a1.w};
#pragma unroll
            for (int i = 0; i < 8; i++) {
                acc1[i][0] += ar[i] * b.x; acc1[i][1] += ar[i] * b.y;
                acc1[i][2] += ar[i] * b.z; acc1[i][3] += ar[i] * b.w;
            }
            if (dual) {
                float4 b2 = *(const float4*)&Cs[k][tx * 4];
#pragma unroll
                for (int i = 0; i < 8; i++) {
                    acc2[i][0] += ar[i] * b2.x; acc2[i][1] += ar[i] * b2.y;
                    acc2[i][2] += ar[i] * b2.z; acc2[i][3] += ar[i] * b2.w;
                }
            }
        }
        __syncthreads();
    }
    // epilogue: activation + store H
#pragma unroll
    for (int i = 0; i < 8; i++) {
        int row = (i < 4) ? (ty * 4 + i) : (64 + ty * 4 + (i - 4));
        if (rm + row >= cnt) continue;
        float4 hv;
        float* hp = (float*)&hv;
#pragma unroll
        for (int j = 0; j < 4; j++) {
            float h;
            if (act == 0) {
                float h1 = acc1[i][j], h2 = acc2[i][j];
                float sg = 1.f / (1.f + expf(-h2));
                h = h2 * sg * h2 * h1;              // silu(h2)*h2*h1
            } else if (act == 1) {
                float u = acc1[i][j];
                h = 0.5f * u * (1.f + erff(u * 0.70710678118654752f));
            } else {
                h = fmaxf(acc1[i][j], 0.f);
            }
            hp[j] = h;
        }
        *(float4*)(g_H + (size_t)(e * SEGCAP + rm + row) * DF + cn + tx * 4) = hv;
    }
}

// GEMM2: Y[cnt, DM] = H_seg @ W3[DF, DM]
__global__ void __launch_bounds__(256) k_gemm2(const float* __restrict__ w3) {
    int e   = blockIdx.z;
    int cnt = min(g_cursor[e], SEGCAP);
    int rm  = blockIdx.y * 128;
    if (rm >= cnt) return;
    int cn = blockIdx.x * 64;

    __shared__ float As[16][128];
    __shared__ float Bs[16][64];

    int tid = threadIdx.x;
    int ty = tid >> 4, tx = tid & 15;
    float acc[8][4];
#pragma unroll
    for (int i = 0; i < 8; i++)
#pragma unroll
        for (int j = 0; j < 4; j++) acc[i][j] = 0.f;

    const float* A = g_H + (size_t)(e * SEGCAP + rm) * DF;
    const float* B = w3 + (size_t)e * DF * DM + cn;

    for (int kt = 0; kt < DF; kt += 16) {
#pragma unroll
        for (int l = 0; l < 2; l++) {
            int idx = tid + l * 256;
            int row = idx >> 2;
            int kk  = (idx & 3) << 2;
            float4 v = make_float4(0.f, 0.f, 0.f, 0.f);
            if (rm + row < cnt)
                v = *(const float4*)(A + (size_t)row * DF + kt + kk);
            As[kk + 0][row] = v.x; As[kk + 1][row] = v.y;
            As[kk + 2][row] = v.z; As[kk + 3][row] = v.w;
        }
        {
            int kk = tid >> 4, c = (tid & 15) << 2;
            *(float4*)&Bs[kk][c] = *(const float4*)(B + (size_t)(kt + kk) * DM + c);
        }
        __syncthreads();
#pragma unroll
        for (int k = 0; k < 16; k++) {
            float4 a0 = *(const float4*)&As[k][ty * 4];
            float4 a1 = *(const float4*)&As[k][ty * 4 + 64];
            float4 b  = *(const float4*)&Bs[k][tx * 4];
            float ar[8] = {a0.x, a0.y, a0.z, a0.w, a1.x, a1.y, a1.z, a1.w};
#pragma unroll
            for (int i = 0; i < 8; i++) {
                acc[i][0] += ar[i] * b.x; acc[i][1] += ar[i] * b.y;
                acc[i][2] += ar[i] * b.z; acc[i][3] += ar[i] * b.w;
            }
        }
        __syncthreads();
    }
#pragma unroll
    for (int i = 0; i < 8; i++) {
        int row = (i < 4) ? (ty * 4 + i) : (64 + ty * 4 + (i - 4));
        if (rm + row >= cnt) continue;
        float4 v = make_float4(acc[i][0], acc[i][1], acc[i][2], acc[i][3]);
        *(float4*)(g_Y + (size_t)(e * SEGCAP + rm + row) * DM + cn + tx * 4) = v;
    }
}

// LN2 with residual: Y[p,:] = LN(x[n] + Y[p]; ln2_w[e], ln2_b[e])  (in place)
__global__ void k_ln2(const float* __restrict__ x,
                      const float* __restrict__ ln2w,
                      const float* __restrict__ ln2b) {
    int p = blockIdx.x;
    int e = p / SEGCAP, i = p % SEGCAP;
    int cnt = min(g_cursor[e], SEGCAP);
    if (i >= cnt) return;
    int n = g_pair_token[p];
    float4*       yr = (float4*)(g_Y + (size_t)p * DM);
    const float4* xr = (const float4*)(x + (size_t)n * DM);
    float4 v = yr[threadIdx.x];
    float4 xv = xr[threadIdx.x];
    v.x += xv.x; v.y += xv.y; v.z += xv.z; v.w += xv.w;
    float s  = v.x + v.y + v.z + v.w;
    float ss = v.x * v.x + v.y * v.y + v.z * v.z + v.w * v.w;
    float m, r;
    row_stats_256(s, ss, DM, m, r);
    float4 w = ((const float4*)(ln2w + (size_t)e * DM))[threadIdx.x];
    float4 b = ((const float4*)(ln2b + (size_t)e * DM))[threadIdx.x];
    float4 o;
    o.x = (v.x - m) * r * w.x + b.x;
    o.y = (v.y - m) * r * w.y + b.y;
    o.z = (v.z - m) * r * w.z + b.z;
    o.w = (v.w - m) * r * w.w + b.w;
    yr[threadIdx.x] = o;
}

// combine the K=2 expert outputs per token + cluster LN
__global__ void k_combine(const float* __restrict__ cw, const float* __restrict__ cb,
                          float* __restrict__ out) {
    int n  = blockIdx.x;
    int p0 = g_pair_id[n * TOPK + 0], p1 = g_pair_id[n * TOPK + 1];
    float w0 = g_wf[n * TOPK + 0], w1 = g_wf[n * TOPK + 1];
    const float4* y0 = (const float4*)(g_Y + (size_t)p0 * DM);
    const float4* y1 = (const float4*)(g_Y + (size_t)p1 * DM);
    float4 a = y0[threadIdx.x], b = y1[threadIdx.x];
    float4 c;
    c.x = w0 * a.x + w1 * b.x;
    c.y = w0 * a.y + w1 * b.y;
    c.z = w0 * a.z + w1 * b.z;
    c.w = w0 * a.w + w1 * b.w;
    float s  = c.x + c.y + c.z + c.w;
    float ss = c.x * c.x + c.y * c.y + c.z * c.z + c.w * c.w;
    float m, r;
    row_stats_256(s, ss, DM, m, r);
    float4 W = ((const float4*)cw)[threadIdx.x];
    float4 B = ((const float4*)cb)[threadIdx.x];
    float4 o;
    o.x = (c.x - m) * r * W.x + B.x;
    o.y = (c.y - m) * r * W.y + B.y;
    o.z = (c.z - m) * r * W.z + B.z;
    o.w = (c.w - m) * r * W.w + B.w;
    ((float4*)(out + (size_t)n * DM))[threadIdx.x] = o;
}

// ---------------- launch ----------------
extern "C" void kernel_launch(void* const* d_in, const int* in_sizes, int n_in,
                              void* d_out, int out_size) {
    const float* x    = (const float*)d_in[0];
    const float* ew   = (const float*)d_in[1];
    const int*   idx  = (const int*)  d_in[2];
    const float* ln1w = (const float*)d_in[3];
    const float* ln1b = (const float*)d_in[4];
    const float* w1   = (const float*)d_in[5];
    const float* w2   = (const float*)d_in[6];
    const float* w3   = (const float*)d_in[7];
    const float* ln2w = (const float*)d_in[8];
    const float* ln2b = (const float*)d_in[9];
    const float* cw   = (const float*)d_in[10];
    const float* cb   = (const float*)d_in[11];
    const float* cu   = (const float*)d_in[12];
    const float* cap  = (const float*)d_in[13];
    float* out = (float*)d_out;

    k_init<<<1, 32>>>();
    k_stats<<<NTOK, 256>>>(x);
    k_route<<<NTOK / 256, 256>>>(ew, idx, cu, cap);
    k_gather<<<PTOT, 256>>>(x, ln1w, ln1b);
    k_gemm1<<<dim3(DF / 64, SEGCAP / 128, NEXP), 256>>>(w1, w2);
    k_gemm2<<<dim3(DM / 64, SEGCAP / 128, NEXP), 256>>>(w3);
    k_ln2<<<PTOT, 256>>>(x, ln2w, ln2b);
    k_combine<<<NTOK, 256>>>(cw, cb, out);
}

// round 2
// speedup vs baseline: 4.0900x; 4.0900x over previous
#include <cuda_runtime.h>
#include <math.h>
#include <stdint.h>

#define NEXP   8
#define DM     1024
#define DF     4096
#define NTOK   8192
#define TOPK   2
#define SEGCAP 4096
#define PTOT   (NEXP * SEGCAP)
#define LN_EPS 1e-5f

// ---------------- scratch (device globals: allocation-free) ----------------
__device__ int   g_cursor[NEXP];
__device__ int   g_pair_token[PTOT];
__device__ int   g_pair_id[NTOK * TOPK];
__device__ float g_wf[NTOK * TOPK];
__device__ float g_mean[NTOK];
__device__ float g_rstd[NTOK];
__device__ float g_Xg[(size_t)PTOT * DM];   // gathered LN1(x) per pair
__device__ float g_H [(size_t)PTOT * DF];   // activated hidden per pair
__device__ float g_Y [(size_t)PTOT * DM];   // expert output (then LN2'd in place)

// ---------------- utilities ----------------
__device__ __forceinline__ void row_stats_256(float s, float ss, int nelem,
                                              float& m_out, float& r_out) {
    __shared__ float sm[8], sq[8];
    int lane = threadIdx.x & 31, w = threadIdx.x >> 5;
#pragma unroll
    for (int o = 16; o; o >>= 1) {
        s  += __shfl_down_sync(0xffffffffu, s,  o);
        ss += __shfl_down_sync(0xffffffffu, ss, o);
    }
    if (lane == 0) { sm[w] = s; sq[w] = ss; }
    __syncthreads();
    if (threadIdx.x == 0) {
        float ts = 0.f, tq = 0.f;
#pragma unroll
        for (int j = 0; j < 8; j++) { ts += sm[j]; tq += sq[j]; }
        float m = ts / (float)nelem;
        float v = tq / (float)nelem - m * m;
        sm[0] = m; sq[0] = rsqrtf(v + LN_EPS);
    }
    __syncthreads();
    m_out = sm[0];
    r_out = sq[0];
}

__device__ __forceinline__ void cpa16(float* dst, const float* src) {
    unsigned d = (unsigned)__cvta_generic_to_shared(dst);
    asm volatile("cp.async.cg.shared.global [%0], [%1], 16;\n" :: "r"(d), "l"(src));
}

#define MMA_TF32(d, a, b)                                                     \
    asm volatile("mma.sync.aligned.m16n8k8.row.col.f32.tf32.tf32.f32 "        \
                 "{%0,%1,%2,%3}, {%4,%5,%6,%7}, {%8,%9}, {%0,%1,%2,%3};\n"    \
                 : "+f"((d)[0]), "+f"((d)[1]), "+f"((d)[2]), "+f"((d)[3])     \
                 : "r"((a)[0]), "r"((a)[1]), "r"((a)[2]), "r"((a)[3]),        \
                   "r"((b)[0]), "r"((b)[1]))

// smem strides (floats): A rows padded 32->36, B rows padded 64->72
#define AST 36
#define BST 72
#define A_STAGE (128 * AST)
#define B_STAGE (32 * BST)

__device__ __forceinline__ void stage_A(float* dst, const float* A, int lda,
                                        int kt, int tid) {
#pragma unroll
    for (int t = 0; t < 8; t++) {
        int idx = tid + t * 128;          // 0..1023 float4s
        int row = idx >> 3, cg = (idx & 7) << 2;
        cpa16(&dst[row * AST + cg], A + (size_t)row * lda + kt + cg);
    }
}
__device__ __forceinline__ void stage_B(float* dst, const float* B, int ldb,
                                        int kt, int tid) {
#pragma unroll
    for (int t = 0; t < 4; t++) {
        int idx = tid + t * 128;          // 0..511 float4s
        int row = idx >> 4, cg = (idx & 15) << 2;
        cpa16(&dst[row * BST + cg], B + (size_t)(kt + row) * ldb + cg);
    }
}

__device__ __forceinline__ float act_eval(int act, float v1, float v2) {
    if (act == 0) {                        // swiglu: silu(h2)*h2*h1
        float sg = 1.f / (1.f + expf(-v2));
        return v2 * sg * v2 * v1;
    } else if (act == 1) {                 // exact gelu
        return 0.5f * v1 * (1.f + erff(v1 * 0.70710678118654752f));
    }
    return fmaxf(v1, 0.f);                 // relu
}

// ---------------- kernels ----------------
__global__ void k_init() {
    if (threadIdx.x < NEXP) g_cursor[threadIdx.x] = 0;
}

__global__ void k_stats(const float* __restrict__ x) {
    int n = blockIdx.x;
    const float4* xr = (const float4*)(x + (size_t)n * DM);
    float4 v = xr[threadIdx.x];
    float s  = v.x + v.y + v.z + v.w;
    float ss = v.x * v.x + v.y * v.y + v.z * v.z + v.w * v.w;
    float m, r;
    row_stats_256(s, ss, DM, m, r);
    if (threadIdx.x == 0) { g_mean[n] = m; g_rstd[n] = r; }
}

__global__ void k_route(const float* __restrict__ ew, const int* __restrict__ idx,
                        const float* __restrict__ cu, const float* __restrict__ cap) {
    int n = blockIdx.x * blockDim.x + threadIdx.x;
    if (n >= NTOK) return;
    int   e[TOPK];
    float w[TOPK];
#pragma unroll
    for (int k = 0; k < TOPK; k++) {
        e[k] = idx[n * TOPK + k];
        float pen = cu[e[k]] / (cap[e[k]] + 1e-8f);
        pen = fminf(fmaxf(pen, 0.f), 2.f);
        w[k] = ew[n * TOPK + k] * (1.f / (1.f + pen));
    }
    float m  = fmaxf(w[0], w[1]);
    float e0 = expf(w[0] - m), e1 = expf(w[1] - m);
    float inv = 1.f / (e0 + e1);
    g_wf[n * TOPK + 0] = e0 * inv;
    g_wf[n * TOPK + 1] = e1 * inv;
#pragma unroll
    for (int k = 0; k < TOPK; k++) {
        int pos = atomicAdd(&g_cursor[e[k]], 1);
        if (pos >= SEGCAP) pos = SEGCAP - 1;
        int p = e[k] * SEGCAP + pos;
        g_pair_token[p] = n;
        g_pair_id[n * TOPK + k] = p;
    }
}

__global__ void k_gather(const float* __restrict__ x,
                         const float* __restrict__ ln1w,
                         const float* __restrict__ ln1b) {
    int p = blockIdx.x;
    int e = p / SEGCAP, i = p % SEGCAP;
    int cnt = min(g_cursor[e], SEGCAP);
    if (i >= cnt) return;
    int   n = g_pair_token[p];
    float m = g_mean[n], r = g_rstd[n];
    const float4* xr = (const float4*)(x    + (size_t)n * DM);
    const float4* wr = (const float4*)(ln1w + (size_t)e * DM);
    const float4* br = (const float4*)(ln1b + (size_t)e * DM);
    float4*       o  = (float4*)(g_Xg + (size_t)p * DM);
    float4 v = xr[threadIdx.x], w = wr[threadIdx.x], b = br[threadIdx.x];
    float4 t;
    t.x = (v.x - m) * r * w.x + b.x;
    t.y = (v.y - m) * r * w.y + b.y;
    t.z = (v.z - m) * r * w.z + b.z;
    t.w = (v.w - m) * r * w.w + b.w;
    o[threadIdx.x] = t;
}

// GEMM1: H[cnt, DF] = act(Xg @ W1 [, Xg @ W2]); TF32 mma, BM=128 BN=64 BK=32
template <bool DUAL>
__global__ void __launch_bounds__(128) k_gemm1(const float* __restrict__ w1,
                                               const float* __restrict__ w2) {
    int e = blockIdx.z;
    if ((e % 3 == 0) != DUAL) return;
    int cnt = min(g_cursor[e], SEGCAP);
    int rm  = blockIdx.y * 128;
    if (rm >= cnt) return;
    int cn  = blockIdx.x * 64;
    int act = e % 3;

    extern __shared__ float sm_[];
    float* As = sm_;                     // 2 * A_STAGE
    float* Bs = sm_ + 2 * A_STAGE;       // 2 * B_STAGE
    float* Cs = Bs + 2 * B_STAGE;        // 2 * B_STAGE (DUAL only)

    int tid = threadIdx.x;
    int lane = tid & 31, wid = tid >> 5;
    int wm = (wid >> 1) * 64, wn = (wid & 1) * 32;
    int lr = lane >> 2, lc = lane & 3;

    const float* A  = g_Xg + (size_t)(e * SEGCAP + rm) * DM;
    const float* B1 = w1 + (size_t)e * DM * DF + cn;
    const float* B2 = w2 + (size_t)e * DM * DF + cn;

    float acc1[4][4][4];
    float acc2[DUAL ? 4 : 1][DUAL ? 4 : 1][4];
#pragma unroll
    for (int i = 0; i < 4; i++)
#pragma unroll
        for (int j = 0; j < 4; j++)
#pragma unroll
            for (int q = 0; q < 4; q++) acc1[i][j][q] = 0.f;
    if (DUAL) {
#pragma unroll
        for (int i = 0; i < 4; i++)
#pragma unroll
            for (int j = 0; j < 4; j++)
#pragma unroll
                for (int q = 0; q < 4; q++) acc2[i][j][q] = 0.f;
    }

    const int NK = DM / 32;
    stage_A(As, A, DM, 0, tid);
    stage_B(Bs, B1, DF, 0, tid);
    if (DUAL) stage_B(Cs, B2, DF, 0, tid);
    asm volatile("cp.async.commit_group;\n");

    for (int it = 0; it < NK; it++) {
        int buf = it & 1;
        if (it + 1 < NK) {
            int nb = 1 - buf;
            stage_A(As + nb * A_STAGE, A, DM, (it + 1) * 32, tid);
            stage_B(Bs + nb * B_STAGE, B1, DF, (it + 1) * 32, tid);
            if (DUAL) stage_B(Cs + nb * B_STAGE, B2, DF, (it + 1) * 32, tid);
            asm volatile("cp.async.commit_group;\n");
            asm volatile("cp.async.wait_group 1;\n");
        } else {
            asm volatile("cp.async.wait_group 0;\n");
        }
        __syncthreads();
        const float* AsS = As + buf * A_STAGE;
        const float* BsS = Bs + buf * B_STAGE;
        const float* CsS = Cs + buf * B_STAGE;
#pragma unroll
        for (int ks = 0; ks < 4; ks++) {
            int k8 = ks * 8;
            uint32_t a[4][4];
#pragma unroll
            for (int mt = 0; mt < 4; mt++) {
                const float* ap = AsS + (wm + mt * 16 + lr) * AST + k8 + lc;
                a[mt][0] = __float_as_uint(ap[0]);
                a[mt][2] = __float_as_uint(ap[4]);
                a[mt][1] = __float_as_uint(ap[8 * AST]);
                a[mt][3] = __float_as_uint(ap[8 * AST + 4]);
            }
            uint32_t b[4][2];
#pragma unroll
            for (int nt = 0; nt < 4; nt++) {
                const float* bp = BsS + (k8 + lc) * BST + wn + nt * 8 + lr;
                b[nt][0] = __float_as_uint(bp[0]);
                b[nt][1] = __float_as_uint(bp[4 * BST]);
            }
#pragma unroll
            for (int mt = 0; mt < 4; mt++)
#pragma unroll
                for (int nt = 0; nt < 4; nt++)
                    MMA_TF32(acc1[mt][nt], a[mt], b[nt]);
            if (DUAL) {
                uint32_t b2[4][2];
#pragma unroll
                for (int nt = 0; nt < 4; nt++) {
                    const float* bp = CsS + (k8 + lc) * BST + wn + nt * 8 + lr;
                    b2[nt][0] = __float_as_uint(bp[0]);
                    b2[nt][1] = __float_as_uint(bp[4 * BST]);
                }
#pragma unroll
                for (int mt = 0; mt < 4; mt++)
#pragma unroll
                    for (int nt = 0; nt < 4; nt++)
                        MMA_TF32(acc2[mt][nt], a[mt], b2[nt]);
            }
        }
        __syncthreads();
    }

    // epilogue: activation + store float2
#pragma unroll
    for (int mt = 0; mt < 4; mt++) {
        int r0 = rm + wm + mt * 16 + lr;
#pragma unroll
        for (int nt = 0; nt < 4; nt++) {
            int c = cn + wn + nt * 8 + lc * 2;
            if (r0 < cnt) {
                float2 v;
                v.x = act_eval(act, acc1[mt][nt][0], DUAL ? acc2[mt][nt][0] : 0.f);
                v.y = act_eval(act, acc1[mt][nt][1], DUAL ? acc2[mt][nt][1] : 0.f);
                *(float2*)(g_H + (size_t)(e * SEGCAP + r0) * DF + c) = v;
            }
            if (r0 + 8 < cnt) {
                float2 v;
                v.x = act_eval(act, acc1[mt][nt][2], DUAL ? acc2[mt][nt][2] : 0.f);
                v.y = act_eval(act, acc1[mt][nt][3], DUAL ? acc2[mt][nt][3] : 0.f);
                *(float2*)(g_H + (size_t)(e * SEGCAP + r0 + 8) * DF + c) = v;
            }
        }
    }
}

// GEMM2: Y[cnt, DM] = H @ W3; TF32 mma, same tiling, K=DF
__global__ void __launch_bounds__(128) k_gemm2(const float* __restrict__ w3) {
    int e = blockIdx.z;
    int cnt = min(g_cursor[e], SEGCAP);
    int rm  = blockIdx.y * 128;
    if (rm >= cnt) return;
    int cn  = blockIdx.x * 64;

    extern __shared__ float sm_[];
    float* As = sm_;
    float* Bs = sm_ + 2 * A_STAGE;

    int tid = threadIdx.x;
    int lane = tid & 31, wid = tid >> 5;
    int wm = (wid >> 1) * 64, wn = (wid & 1) * 32;
    int lr = lane >> 2, lc = lane & 3;

    const float* A = g_H + (size_t)(e * SEGCAP + rm) * DF;
    const float* B = w3 + (size_t)e * DF * DM + cn;

    float acc[4][4][4];
#pragma unroll
    for (int i = 0; i < 4; i++)
#pragma unroll
        for (int j = 0; j < 4; j++)
#pragma unroll
            for (int q = 0; q < 4; q++) acc[i][j][q] = 0.f;

    const int NK = DF / 32;
    stage_A(As, A, DF, 0, tid);
    stage_B(Bs, B, DM, 0, tid);
    asm volatile("cp.async.commit_group;\n");

    for (int it = 0; it < NK; it++) {
        int buf = it & 1;
        if (it + 1 < NK) {
            int nb = 1 - buf;
            stage_A(As + nb * A_STAGE, A, DF, (it + 1) * 32, tid);
            stage_B(Bs + nb * B_STAGE, B, DM, (it + 1) * 32, tid);
            asm volatile("cp.async.commit_group;\n");
            asm volatile("cp.async.wait_group 1;\n");
        } else {
            asm volatile("cp.async.wait_group 0;\n");
        }
        __syncthreads();
        const float* AsS = As + buf * A_STAGE;
        const float* BsS = Bs + buf * B_STAGE;
#pragma unroll
        for (int ks = 0; ks < 4; ks++) {
            int k8 = ks * 8;
            uint32_t a[4][4];
#pragma unroll
            for (int mt = 0; mt < 4; mt++) {
                const float* ap = AsS + (wm + mt * 16 + lr) * AST + k8 + lc;
                a[mt][0] = __float_as_uint(ap[0]);
                a[mt][2] = __float_as_uint(ap[4]);
                a[mt][1] = __float_as_uint(ap[8 * AST]);
                a[mt][3] = __float_as_uint(ap[8 * AST + 4]);
            }
            uint32_t b[4][2];
#pragma unroll
            for (int nt = 0; nt < 4; nt++) {
                const float* bp = BsS + (k8 + lc) * BST + wn + nt * 8 + lr;
                b[nt][0] = __float_as_uint(bp[0]);
                b[nt][1] = __float_as_uint(bp[4 * BST]);
            }
#pragma unroll
            for (int mt = 0; mt < 4; mt++)
#pragma unroll
                for (int nt = 0; nt < 4; nt++)
                    MMA_TF32(acc[mt][nt], a[mt], b[nt]);
        }
        __syncthreads();
    }

#pragma unroll
    for (int mt = 0; mt < 4; mt++) {
        int r0 = rm + wm + mt * 16 + lr;
#pragma unroll
        for (int nt = 0; nt < 4; nt++) {
            int c = cn + wn + nt * 8 + lc * 2;
            if (r0 < cnt)
                *(float2*)(g_Y + (size_t)(e * SEGCAP + r0) * DM + c) =
                    make_float2(acc[mt][nt][0], acc[mt][nt][1]);
            if (r0 + 8 < cnt)
                *(float2*)(g_Y + (size_t)(e * SEGCAP + r0 + 8) * DM + c) =
                    make_float2(acc[mt][nt][2], acc[mt][nt][3]);
        }
    }
}

__global__ void k_ln2(const float* __restrict__ x,
                      const float* __restrict__ ln2w,
                      const float* __restrict__ ln2b) {
    int p = blockIdx.x;
    int e = p / SEGCAP, i = p % SEGCAP;
    int cnt = min(g_cursor[e], SEGCAP);
    if (i >= cnt) return;
    int n = g_pair_token[p];
    float4*       yr = (float4*)(g_Y + (size_t)p * DM);
    const float4* xr = (const float4*)(x + (size_t)n * DM);
    float4 v = yr[threadIdx.x];
    float4 xv = xr[threadIdx.x];
    v.x += xv.x; v.y += xv.y; v.z += xv.z; v.w += xv.w;
    float s  = v.x + v.y + v.z + v.w;
    float ss = v.x * v.x + v.y * v.y + v.z * v.z + v.w * v.w;
    float m, r;
    row_stats_256(s, ss, DM, m, r);
    float4 w = ((const float4*)(ln2w + (size_t)e * DM))[threadIdx.x];
    float4 b = ((const float4*)(ln2b + (size_t)e * DM))[threadIdx.x];
    float4 o;
    o.x = (v.x - m) * r * w.x + b.x;
    o.y = (v.y - m) * r * w.y + b.y;
    o.z = (v.z - m) * r * w.z + b.z;
    o.w = (v.w - m) * r * w.w + b.w;
    yr[threadIdx.x] = o;
}

__global__ void k_combine(const float* __restrict__ cw, const float* __restrict__ cb,
                          float* __restrict__ out) {
    int n  = blockIdx.x;
    int p0 = g_pair_id[n * TOPK + 0], p1 = g_pair_id[n * TOPK + 1];
    float w0 = g_wf[n * TOPK + 0], w1 = g_wf[n * TOPK + 1];
    const float4* y0 = (const float4*)(g_Y + (size_t)p0 * DM);
    const float4* y1 = (const float4*)(g_Y + (size_t)p1 * DM);
    float4 a = y0[threadIdx.x], b = y1[threadIdx.x];
    float4 c;
    c.x = w0 * a.x + w1 * b.x;
    c.y = w0 * a.y + w1 * b.y;
    c.z = w0 * a.z + w1 * b.z;
    c.w = w0 * a.w + w1 * b.w;
    float s  = c.x + c.y + c.z + c.w;
    float ss = c.x * c.x + c.y * c.y + c.z * c.z + c.w * c.w;
    float m, r;
    row_stats_256(s, ss, DM, m, r);
    float4 W = ((const float4*)cw)[threadIdx.x];
    float4 B = ((const float4*)cb)[threadIdx.x];
    float4 o;
    o.x = (c.x - m) * r * W.x + B.x;
    o.y = (c.y - m) * r * W.y + B.y;
    o.z = (c.z - m) * r * W.z + B.z;
    o.w = (c.w - m) * r * W.w + B.w;
    ((float4*)(out + (size_t)n * DM))[threadIdx.x] = o;
}

// ---------------- launch ----------------
#define SMEM_G1_DUAL ((2 * A_STAGE + 4 * B_STAGE) * 4)
#define SMEM_G1_MONO ((2 * A_STAGE + 2 * B_STAGE) * 4)
#define SMEM_G2      ((2 * A_STAGE + 2 * B_STAGE) * 4)

extern "C" void kernel_launch(void* const* d_in, const int* in_sizes, int n_in,
                              void* d_out, int out_size) {
    const float* x    = (const float*)d_in[0];
    const float* ew   = (const float*)d_in[1];
    const int*   idx  = (const int*)  d_in[2];
    const float* ln1w = (const float*)d_in[3];
    const float* ln1b = (const float*)d_in[4];
    const float* w1   = (const float*)d_in[5];
    const float* w2   = (const float*)d_in[6];
    const float* w3   = (const float*)d_in[7];
    const float* ln2w = (const float*)d_in[8];
    const float* ln2b = (const float*)d_in[9];
    const float* cw   = (const float*)d_in[10];
    const float* cb   = (const float*)d_in[11];
    const float* cu   = (const float*)d_in[12];
    const float* cap  = (const float*)d_in[13];
    float* out = (float*)d_out;

    cudaFuncSetAttribute(k_gemm1<true>,  cudaFuncAttributeMaxDynamicSharedMemorySize, SMEM_G1_DUAL);
    cudaFuncSetAttribute(k_gemm1<false>, cudaFuncAttributeMaxDynamicSharedMemorySize, SMEM_G1_MONO);
    cudaFuncSetAttribute(k_gemm2,        cudaFuncAttributeMaxDynamicSharedMemorySize, SMEM_G2);

    k_init<<<1, 32>>>();
    k_stats<<<NTOK, 256>>>(x);
    k_route<<<NTOK / 256, 256>>>(ew, idx, cu, cap);
    k_gather<<<PTOT, 256>>>(x, ln1w, ln1b);
    dim3 g1(DF / 64, SEGCAP / 128, NEXP);
    k_gemm1<true ><<<g1, 128, SMEM_G1_DUAL>>>(w1, w2);
    k_gemm1<false><<<g1, 128, SMEM_G1_MONO>>>(w1, w2);
    dim3 g2(DM / 64, SEGCAP / 128, NEXP);
    k_gemm2<<<g2, 128, SMEM_G2>>>(w3);
    k_ln2<<<PTOT, 256>>>(x, ln2w, ln2b);
    k_combine<<<NTOK, 256>>>(cw, cb, out);
}

// round 4
// speedup vs baseline: 6.2165x; 1.5199x over previous
#include <cuda_runtime.h>
#include <cuda_fp16.h>
#include <math.h>
#include <stdint.h>

#define NEXP   8
#define DM     1024
#define DF     4096
#define NTOK   8192
#define TOPK   2
#define NPAIR  (NTOK * TOPK)
#define SEGCAP 4096
#define PTOT   (NEXP * SEGCAP)
#define LN_EPS 1e-5f

// ---------------- scratch (device globals: allocation-free) ----------------
__device__ int    g_cursor[NEXP];
__device__ int    g_pair_id[NPAIR];
__device__ float  g_wf[NPAIR];
__device__ float  g_mean[NTOK];
__device__ float  g_rstd[NTOK];
__device__ __half g_w1h[(size_t)NEXP * DM * DF];
__device__ __half g_w2h[(size_t)NEXP * DM * DF];
__device__ __half g_w3h[(size_t)NEXP * DF * DM];
__device__ __half g_XgH[(size_t)PTOT * DM];   // gathered LN1(x), fp16
__device__ __half g_Hh [(size_t)PTOT * DF];   // activated hidden, fp16
__device__ float  g_Y  [(size_t)PTOT * DM];   // expert output fp32

// ---------------- helpers ----------------
__device__ __forceinline__ uint32_t smem_u32(const void* p) {
    uint32_t a;
    asm("{ .reg .u64 t; cvta.to.shared.u64 t, %1; cvt.u32.u64 %0, t; }"
        : "=r"(a) : "l"(p));
    return a;
}
__device__ __forceinline__ void cpa16(void* dst, const void* src) {
    unsigned d = smem_u32(dst);
    asm volatile("cp.async.cg.shared.global [%0], [%1], 16;\n" :: "r"(d), "l"(src));
}
__device__ __forceinline__ void ldmA4(uint32_t* r, uint32_t a) {
    asm volatile("ldmatrix.sync.aligned.m8n8.x4.shared.b16 {%0,%1,%2,%3}, [%4];"
                 : "=r"(r[0]), "=r"(r[1]), "=r"(r[2]), "=r"(r[3]) : "r"(a));
}
__device__ __forceinline__ void ldmBT4(uint32_t* r, uint32_t a) {
    asm volatile("ldmatrix.sync.aligned.m8n8.x4.trans.shared.b16 {%0,%1,%2,%3}, [%4];"
                 : "=r"(r[0]), "=r"(r[1]), "=r"(r[2]), "=r"(r[3]) : "r"(a));
}
#define MMA_F16(d, a, b)                                                      \
    asm volatile("mma.sync.aligned.m16n8k16.row.col.f32.f16.f16.f32 "         \
                 "{%0,%1,%2,%3}, {%4,%5,%6,%7}, {%8,%9}, {%0,%1,%2,%3};\n"    \
                 : "+f"((d)[0]), "+f"((d)[1]), "+f"((d)[2]), "+f"((d)[3])     \
                 : "r"((a)[0]), "r"((a)[1]), "r"((a)[2]), "r"((a)[3]),        \
                   "r"((b)[0]), "r"((b)[1]))

__device__ __forceinline__ void row_stats_256(float s, float ss, int nelem,
                                              float& m_out, float& r_out) {
    __shared__ float sm[8], sq[8];
    int lane = threadIdx.x & 31, w = threadIdx.x >> 5;
#pragma unroll
    for (int o = 16; o; o >>= 1) {
        s  += __shfl_down_sync(0xffffffffu, s,  o);
        ss += __shfl_down_sync(0xffffffffu, ss, o);
    }
    if (lane == 0) { sm[w] = s; sq[w] = ss; }
    __syncthreads();
    if (threadIdx.x == 0) {
        float ts = 0.f, tq = 0.f;
#pragma unroll
        for (int j = 0; j < 8; j++) { ts += sm[j]; tq += sq[j]; }
        float m = ts / (float)nelem;
        float v = tq / (float)nelem - m * m;
        sm[0] = m; sq[0] = rsqrtf(v + LN_EPS);
    }
    __syncthreads();
    m_out = sm[0];
    r_out = sq[0];
}

__device__ __forceinline__ float act_eval(int act, float v1, float v2) {
    if (act == 0) {                        // swiglu: silu(h2)*h2*h1
        float sg = 1.f / (1.f + expf(-v2));
        return v2 * sg * v2 * v1;
    } else if (act == 1) {                 // exact gelu
        return 0.5f * v1 * (1.f + erff(v1 * 0.70710678118654752f));
    } else if (act == 2) {
        return fmaxf(v1, 0.f);             // relu
    }
    return v1;                             // identity (GEMM2)
}

// ---------------- small kernels ----------------
__global__ void k_init() {
    if (threadIdx.x < NEXP) g_cursor[threadIdx.x] = 0;
}

// fp32 -> fp16 (4 elems/thread, vectorized)
__global__ void k_cvt(const float* __restrict__ s, __half* __restrict__ d) {
    size_t i = ((size_t)blockIdx.x * 256 + threadIdx.x) * 4;
    float4 v = *(const float4*)(s + i);
    __half2 h0 = __floats2half2_rn(v.x, v.y);
    __half2 h1 = __floats2half2_rn(v.z, v.w);
    uint2 u;
    u.x = *(uint32_t*)&h0;
    u.y = *(uint32_t*)&h1;
    *(uint2*)(d + i) = u;
}

__global__ void k_stats(const float* __restrict__ x) {
    int n = blockIdx.x;
    const float4* xr = (const float4*)(x + (size_t)n * DM);
    float4 v = xr[threadIdx.x];
    float s  = v.x + v.y + v.z + v.w;
    float ss = v.x * v.x + v.y * v.y + v.z * v.z + v.w * v.w;
    float m, r;
    row_stats_256(s, ss, DM, m, r);
    if (threadIdx.x == 0) { g_mean[n] = m; g_rstd[n] = r; }
}

__global__ void k_route(const float* __restrict__ ew, const int* __restrict__ idx,
                        const float* __restrict__ cu, const float* __restrict__ cap) {
    int n = blockIdx.x * blockDim.x + threadIdx.x;
    if (n >= NTOK) return;
    int   e[TOPK];
    float w[TOPK];
#pragma unroll
    for (int k = 0; k < TOPK; k++) {
        e[k] = idx[n * TOPK + k];
        float pen = cu[e[k]] / (cap[e[k]] + 1e-8f);
        pen = fminf(fmaxf(pen, 0.f), 2.f);
        w[k] = ew[n * TOPK + k] * (1.f / (1.f + pen));
    }
    float m  = fmaxf(w[0], w[1]);
    float e0 = expf(w[0] - m), e1 = expf(w[1] - m);
    float inv = 1.f / (e0 + e1);
    g_wf[n * TOPK + 0] = e0 * inv;
    g_wf[n * TOPK + 1] = e1 * inv;
#pragma unroll
    for (int k = 0; k < TOPK; k++) {
        int pos = atomicAdd(&g_cursor[e[k]], 1);
        if (pos >= SEGCAP) pos = SEGCAP - 1;
        g_pair_id[n * TOPK + k] = e[k] * SEGCAP + pos;
    }
}

// gather + LN1 -> fp16 Xg ; one block per live pair
__global__ void k_gather(const float* __restrict__ x,
                         const float* __restrict__ ln1w,
                         const float* __restrict__ ln1b) {
    int bidx = blockIdx.x;
    int p = g_pair_id[bidx];
    int n = bidx >> 1;
    int e = p / SEGCAP;
    float m = g_mean[n], r = g_rstd[n];
    const float4* xr = (const float4*)(x    + (size_t)n * DM);
    const float4* wr = (const float4*)(ln1w + (size_t)e * DM);
    const float4* br = (const float4*)(ln1b + (size_t)e * DM);
    float4 v = xr[threadIdx.x], w = wr[threadIdx.x], b = br[threadIdx.x];
    __half2 h0 = __floats2half2_rn((v.x - m) * r * w.x + b.x,
                                   (v.y - m) * r * w.y + b.y);
    __half2 h1 = __floats2half2_rn((v.z - m) * r * w.z + b.z,
                                   (v.w - m) * r * w.w + b.w);
    uint2 u;
    u.x = *(uint32_t*)&h0;
    u.y = *(uint32_t*)&h1;
    *(uint2*)(g_XgH + (size_t)p * DM + threadIdx.x * 4) = u;
}

// ---------------- fp16 mma.sync GEMM ----------------
// BM=128, BN=128, BK=32, 256 thr, 8 warps in 4(M)x2(N); warp tile 32x64.
// A: [M, K] fp16 smem rows padded to 40 halves; B: [K, N] rows padded to 136.
// mode: 0 = GEMM1 swiglu (DUAL), 1 = GEMM1 gelu/relu, 2 = GEMM2.
#define AHS 40
#define BHS 136
#define ASZ (128 * AHS * 2)
#define BSZ (32 * BHS * 2)

template <bool DUAL>
__global__ void __launch_bounds__(256) k_fmm(const __half* __restrict__ A, int lda, int NK,
                                             const __half* __restrict__ B1,
                                             const __half* __restrict__ B2, int ldb,
                                             __half* __restrict__ OutH,
                                             float* __restrict__ OutF, int ldo,
                                             int mode) {
    int e = blockIdx.z;
    if (mode == 0 && (e % 3) != 0) return;
    if (mode == 1 && (e % 3) == 0) return;
    int cnt = min(g_cursor[e], SEGCAP);
    int rm = blockIdx.y * 128;
    if (rm >= cnt) return;
    int cn  = blockIdx.x * 128;
    int act = (mode == 2) ? 3 : (e % 3);

    extern __shared__ char sb[];
    char* Ab = sb;
    char* Bb = sb + 2 * ASZ;
    char* Cb = Bb + 2 * BSZ;

    int tid = threadIdx.x, lane = tid & 31, wid = tid >> 5;
    int wm = (wid >> 1) * 32, wn = (wid & 1) * 64;

    const __half* Ae  = A + (size_t)(e * SEGCAP + rm) * lda;
    const __half* B1e = B1 + (size_t)e * (size_t)(NK * 32) * ldb + cn;
    const __half* B2e = DUAL ? (B2 + (size_t)e * (size_t)(NK * 32) * ldb + cn)
                             : (const __half*)0;

    float acc1[2][8][4];
    float acc2[DUAL ? 2 : 1][DUAL ? 8 : 1][4];
#pragma unroll
    for (int i = 0; i < 2; i++)
#pragma unroll
        for (int j = 0; j < 8; j++)
#pragma unroll
            for (int q = 0; q < 4; q++) acc1[i][j][q] = 0.f;
    if (DUAL) {
#pragma unroll
        for (int i = 0; i < 2; i++)
#pragma unroll
            for (int j = 0; j < 8; j++)
#pragma unroll
                for (int q = 0; q < 4; q++) acc2[i][j][q] = 0.f;
    }

    auto stA = [&](char* dst, int kt) {
#pragma unroll
        for (int t = 0; t < 2; t++) {
            int idx = tid + t * 256;           // 512 chunks of 16B
            int row = idx >> 2, c = idx & 3;
            cpa16(dst + row * (AHS * 2) + c * 16,
                  Ae + (size_t)row * lda + kt + c * 8);
        }
    };
    auto stB = [&](char* dst, const __half* B, int kt) {
#pragma unroll
        for (int t = 0; t < 2; t++) {
            int idx = tid + t * 256;           // 512 chunks
            int k = idx >> 4, c = idx & 15;
            cpa16(dst + k * (BHS * 2) + c * 16,
                  B + (size_t)(kt + k) * ldb + c * 8);
        }
    };

    stA(Ab, 0);
    stB(Bb, B1e, 0);
    if (DUAL) stB(Cb, B2e, 0);
    asm volatile("cp.async.commit_group;\n");

    int lrow = lane & 15, lhi = (lane >> 4) & 1;

    for (int it = 0; it < NK; it++) {
        int buf = it & 1;
        if (it + 1 < NK) {
            int nb = 1 - buf;
            stA(Ab + nb * ASZ, (it + 1) * 32);
            stB(Bb + nb * BSZ, B1e, (it + 1) * 32);
            if (DUAL) stB(Cb + nb * BSZ, B2e, (it + 1) * 32);
            asm volatile("cp.async.commit_group;\n");
            asm volatile("cp.async.wait_group 1;\n");
        } else {
            asm volatile("cp.async.wait_group 0;\n");
        }
        __syncthreads();
        uint32_t asb = smem_u32(Ab + buf * ASZ);
        uint32_t bsb = smem_u32(Bb + buf * BSZ);
        uint32_t csb = DUAL ? smem_u32(Cb + buf * BSZ) : 0;
#pragma unroll
        for (int ks = 0; ks < 32; ks += 16) {
            uint32_t af[2][4];
#pragma unroll
            for (int mt = 0; mt < 2; mt++)
                ldmA4(af[mt], asb + ((wm + mt * 16 + lrow) * AHS + ks + lhi * 8) * 2);
            uint32_t bf[8][2];
#pragma unroll
            for (int nb4 = 0; nb4 < 4; nb4++) {
                uint32_t r[4];
                ldmBT4(r, bsb + ((ks + lrow) * BHS + wn + nb4 * 16 + lhi * 8) * 2);
                bf[nb4 * 2][0] = r[0]; bf[nb4 * 2][1] = r[1];
                bf[nb4 * 2 + 1][0] = r[2]; bf[nb4 * 2 + 1][1] = r[3];
            }
#pragma unroll
            for (int mt = 0; mt < 2; mt++)
#pragma unroll
                for (int nt = 0; nt < 8; nt++)
                    MMA_F16(acc1[mt][nt], af[mt], bf[nt]);
            if (DUAL) {
#pragma unroll
                for (int nb4 = 0; nb4 < 4; nb4++) {
                    uint32_t r[4];
                    ldmBT4(r, csb + ((ks + lrow) * BHS + wn + nb4 * 16 + lhi * 8) * 2);
                    bf[nb4 * 2][0] = r[0]; bf[nb4 * 2][1] = r[1];
                    bf[nb4 * 2 + 1][0] = r[2]; bf[nb4 * 2 + 1][1] = r[3];
                }
#pragma unroll
                for (int mt = 0; mt < 2; mt++)
#pragma unroll
                    for (int nt = 0; nt < 8; nt++)
                        MMA_F16(acc2[mt][nt], af[mt], bf[nt]);
            }
        }
        __syncthreads();
    }

    // epilogue: c frag rows = lane>>2 (+8), cols = (lane&3)*2 (+1)
#pragma unroll
    for (int mt = 0; mt < 2; mt++) {
        int r0 = rm + wm + mt * 16 + (lane >> 2);
#pragma unroll
        for (int nt = 0; nt < 8; nt++) {
            int col = cn + wn + nt * 8 + (lane & 3) * 2;
#pragma unroll
            for (int hh = 0; hh < 2; hh++) {
                int row = r0 + hh * 8;
                if (row >= cnt) continue;
                float v0 = act_eval(act, acc1[mt][nt][hh * 2],
                                    DUAL ? acc2[mt][nt][hh * 2] : 0.f);
                float v1 = act_eval(act, acc1[mt][nt][hh * 2 + 1],
                                    DUAL ? acc2[mt][nt][hh * 2 + 1] : 0.f);
                if (mode == 2) {
                    *(float2*)(OutF + (size_t)(e * SEGCAP + row) * ldo + col) =
                        make_float2(v0, v1);
                } else {
                    __half2 h = __floats2half2_rn(v0, v1);
                    *(uint32_t*)(OutH + (size_t)(e * SEGCAP + row) * ldo + col) =
                        *(uint32_t*)&h;
                }
            }
        }
    }
}

// LN2 with residual (per live pair)
__global__ void k_ln2(const float* __restrict__ x,
                      const float* __restrict__ ln2w,
                      const float* __restrict__ ln2b) {
    int bidx = blockIdx.x;
    int p = g_pair_id[bidx];
    int n = bidx >> 1;
    int e = p / SEGCAP;
    float4*       yr = (float4*)(g_Y + (size_t)p * DM);
    const float4* xr = (const float4*)(x + (size_t)n * DM);
    float4 v = yr[threadIdx.x];
    float4 xv = xr[threadIdx.x];
    v.x += xv.x; v.y += xv.y; v.z += xv.z; v.w += xv.w;
    float s  = v.x + v.y + v.z + v.w;
    float ss = v.x * v.x + v.y * v.y + v.z * v.z + v.w * v.w;
    float m, r;
    row_stats_256(s, ss, DM, m, r);
    float4 w = ((const float4*)(ln2w + (size_t)e * DM))[threadIdx.x];
    float4 b = ((const float4*)(ln2b + (size_t)e * DM))[threadIdx.x];
    float4 o;
    o.x = (v.x - m) * r * w.x + b.x;
    o.y = (v.y - m) * r * w.y + b.y;
    o.z = (v.z - m) * r * w.z + b.z;
    o.w = (v.w - m) * r * w.w + b.w;
    yr[threadIdx.x] = o;
}

__global__ void k_combine(const float* __restrict__ cw, const float* __restrict__ cb,
                          float* __restrict__ out) {
    int n  = blockIdx.x;
    int p0 = g_pair_id[n * TOPK + 0], p1 = g_pair_id[n * TOPK + 1];
    float w0 = g_wf[n * TOPK + 0], w1 = g_wf[n * TOPK + 1];
    const float4* y0 = (const float4*)(g_Y + (size_t)p0 * DM);
    const float4* y1 = (const float4*)(g_Y + (size_t)p1 * DM);
    float4 a = y0[threadIdx.x], b = y1[threadIdx.x];
    float4 c;
    c.x = w0 * a.x + w1 * b.x;
    c.y = w0 * a.y + w1 * b.y;
    c.z = w0 * a.z + w1 * b.z;
    c.w = w0 * a.w + w1 * b.w;
    float s  = c.x + c.y + c.z + c.w;
    float ss = c.x * c.x + c.y * c.y + c.z * c.z + c.w * c.w;
    float m, r;
    row_stats_256(s, ss, DM, m, r);
    float4 W = ((const float4*)cw)[threadIdx.x];
    float4 B = ((const float4*)cb)[threadIdx.x];
    float4 o;
    o.x = (c.x - m) * r * W.x + B.x;
    o.y = (c.y - m) * r * W.y + B.y;
    o.z = (c.z - m) * r * W.z + B.z;
    o.w = (c.w - m) * r * W.w + B.w;
    ((float4*)(out + (size_t)n * DM))[threadIdx.x] = o;
}

// ---------------- launch ----------------
#define SMEM_DUAL (2 * ASZ + 4 * BSZ)
#define SMEM_MONO (2 * ASZ + 2 * BSZ)

extern "C" void kernel_launch(void* const* d_in, const int* in_sizes, int n_in,
                              void* d_out, int out_size) {
    const float* x    = (const float*)d_in[0];
    const float* ew   = (const float*)d_in[1];
    const int*   idx  = (const int*)  d_in[2];
    const float* ln1w = (const float*)d_in[3];
    const float* ln1b = (const float*)d_in[4];
    const float* w1   = (const float*)d_in[5];
    const float* w2   = (const float*)d_in[6];
    const float* w3   = (const float*)d_in[7];
    const float* ln2w = (const float*)d_in[8];
    const float* ln2b = (const float*)d_in[9];
    const float* cw   = (const float*)d_in[10];
    const float* cb   = (const float*)d_in[11];
    const float* cu   = (const float*)d_in[12];
    const float* cap  = (const float*)d_in[13];
    float* out = (float*)d_out;

    __half *pW1h, *pW2h, *pW3h, *pXg, *pH;
    float* pY;
    cudaGetSymbolAddress((void**)&pW1h, g_w1h);
    cudaGetSymbolAddress((void**)&pW2h, g_w2h);
    cudaGetSymbolAddress((void**)&pW3h, g_w3h);
    cudaGetSymbolAddress((void**)&pXg,  g_XgH);
    cudaGetSymbolAddress((void**)&pH,   g_Hh);
    cudaGetSymbolAddress((void**)&pY,   g_Y);

    cudaFuncSetAttribute(k_fmm<true>,  cudaFuncAttributeMaxDynamicSharedMemorySize, SMEM_DUAL);
    cudaFuncSetAttribute(k_fmm<false>, cudaFuncAttributeMaxDynamicSharedMemorySize, SMEM_MONO);

    // weight conversion (w2 only for swiglu experts 0,3,6)
    const int WBLK = (int)(((size_t)NEXP * DM * DF) / 1024);
    k_cvt<<<WBLK, 256>>>(w1, pW1h);
    k_cvt<<<WBLK, 256>>>(w3, pW3h);
    for (int e = 0; e < NEXP; e += 3)
        k_cvt<<<WBLK / NEXP, 256>>>(w2 + (size_t)e * DM * DF, pW2h + (size_t)e * DM * DF);

    k_init<<<1, 32>>>();
    k_stats<<<NTOK, 256>>>(x);
    k_route<<<NTOK / 256, 256>>>(ew, idx, cu, cap);
    k_gather<<<NPAIR, 256>>>(x, ln1w, ln1b);

    // GEMM1 swiglu experts (dual)
    k_fmm<true><<<dim3(DF / 128, SEGCAP / 128, NEXP), 256, SMEM_DUAL>>>(
        pXg, DM, DM / 32, pW1h, pW2h, DF, pH, (float*)0, DF, 0);
    // GEMM1 gelu/relu experts
    k_fmm<false><<<dim3(DF / 128, SEGCAP / 128, NEXP), 256, SMEM_MONO>>>(
        pXg, DM, DM / 32, pW1h, (const __half*)0, DF, pH, (float*)0, DF, 1);
    // GEMM2
    k_fmm<false><<<dim3(DM / 128, SEGCAP / 128, NEXP), 256, SMEM_MONO>>>(
        pH, DF, DF / 32, pW3h, (const __half*)0, DM, (__half*)0, pY, DM, 2);

    k_ln2<<<NPAIR, 256>>>(x, ln2w, ln2b);
    k_combine<<<NTOK, 256>>>(cw, cb, out);
}